// round 13
// baseline (speedup 1.0000x reference)
#include <cuda_runtime.h>
#include <cuda_bf16.h>

#define NG 10000
#define W 256
#define H 256
#define TSX 32
#define TSY 16
#define TX 8               // tiles per row (32 px wide)
#define TY 16              // tile rows (16 px tall)
#define NTILE (TX * TY)    // 128
#define SEGS 8
#define SEGN (NG / SEGS)   // 1250
#define CAP  SEGN
#define ZSPLIT 4           // 2 segments per z-block

// Static device scratch (no dynamic allocation anywhere)
static __device__ float4 g_parA[NG];                  // cx, cy, ha*log2e, b*log2e
static __device__ float4 g_parB[NG];                  // hc*log2e, log2(op), colR, colG
static __device__ float  g_parC[NG];                  // colB
static __device__ int    g_rng[NG];                   // tx0|tx1<<4|ty0<<8|ty1<<12
static __device__ int    g_tlist[NTILE * SEGS * CAP]; // gid lists (4 B/entry)
static __device__ int    g_tcnt[NTILE * SEGS];
static __device__ float  g_part[ZSPLIT][3 * H * W];
static __device__ int    g_done[NTILE];

__device__ __forceinline__ float fast_tanh(float x) {
    float e;
    asm("ex2.approx.f32 %0, %1;" : "=f"(e) : "f"(x * 2.885390081777927f)); // 2*log2e
    float r;
    asm("rcp.approx.f32 %0, %1;" : "=f"(r) : "f"(1.0f + e));
    return 1.0f - 2.0f * r;
}

// Prep: params + tile ranges; resets per-tile counters (runs first in-stream).
__global__ __launch_bounds__(256) void prep_kernel(
    const float* __restrict__ xyz,
    const float* __restrict__ chol,
    const float* __restrict__ colors,
    const float* __restrict__ opacity) {
    int i = blockIdx.x * 256 + threadIdx.x;
    if (i < NTILE) g_done[i] = 0;
    if (i >= NG) return;
    const float LOG2E = 1.4426950408889634f;
    float cx = 0.5f * W * (fast_tanh(__ldg(xyz + 2 * i)) + 1.0f);
    float cy = 0.5f * H * (fast_tanh(__ldg(xyz + 2 * i + 1)) + 1.0f);
    float L0 = __ldg(chol + 3 * i) + 0.5f;
    float L1 = __ldg(chol + 3 * i + 1);
    float L2 = __ldg(chol + 3 * i + 2) + 0.5f;
    float cxx = L0 * L0;
    float cxy = L0 * L1;
    float cyy = L1 * L1 + L2 * L2;
    float det = cxx * cyy - cxy * cxy;
    float inv = 1.0f / det;
    float op = __ldg(opacity + i);
    float T = __logf(255.0f * op) + 0.05f;

    int tx0 = 15, tx1 = 0, ty0 = 15, ty1 = 0;  // empty sentinel
    if (det > 0.0f && op > 0.0f && T > 0.0f) {
        float rx = sqrtf(2.0f * T * cxx) + 1.0f;
        float ry = sqrtf(2.0f * T * cyy) + 1.0f;
        float xlo = cx - rx, xhi = cx + rx;
        float ylo = cy - ry, yhi = cy + ry;
        if (xhi >= 0.0f && xlo <= (float)(W - 1) &&
            yhi >= 0.0f && ylo <= (float)(H - 1)) {
            tx0 = max(0, (int)floorf(xlo * (1.0f / TSX)));
            tx1 = min(TX - 1, (int)floorf(xhi * (1.0f / TSX)));
            ty0 = max(0, (int)floorf(ylo * (1.0f / TSY)));
            ty1 = min(TY - 1, (int)floorf(yhi * (1.0f / TSY)));
        }
    }
    g_rng[i]  = tx0 | (tx1 << 4) | (ty0 << 8) | (ty1 << 12);
    g_parA[i] = make_float4(cx, cy, 0.5f * cyy * inv * LOG2E, -cxy * inv * LOG2E);
    g_parB[i] = make_float4(0.5f * cxx * inv * LOG2E, __log2f(op),
                            __ldg(colors + 3 * i), __ldg(colors + 3 * i + 1));
    g_parC[i] = __ldg(colors + 3 * i + 2);
}

// Binning: grid (SEGS, TY). Deterministic gid-ordered scatter (gid only, 8 tiles).
__global__ __launch_bounds__(256) void bin_kernel() {
    const int seg = blockIdx.x, row = blockIdx.y;
    const int tid = threadIdx.x, lane = tid & 31, wid = tid >> 5;
    __shared__ unsigned sball[TX][9];
    __shared__ int sbase[TX];
    const int segBase = seg * SEGN;
    const unsigned lmask = (1u << lane) - 1u;

    if (tid < TX) sbase[tid] = 0;
    __syncthreads();

    for (int it = 0; it < (SEGN + 255) / 256; it++) {
        int i = segBase + it * 256 + tid;
        int rng = (i < segBase + SEGN) ? g_rng[i] : 0x0F00;
        int ty0 = (rng >> 8) & 15, ty1 = (rng >> 12) & 15;
        int t0 = rng & 15, t1 = (rng >> 4) & 15;
        bool pass = (ty0 <= row) && (row <= ty1);
        #pragma unroll
        for (int tx = 0; tx < TX; tx++) {
            unsigned b = __ballot_sync(0xffffffffu, pass && (t0 <= tx) && (tx <= t1));
            if (lane == 0) sball[tx][wid] = b;
        }
        __syncthreads();
        if (pass) {
            for (int tx = t0; tx <= t1; tx++) {
                int pos = sbase[tx];
                #pragma unroll
                for (int k = 0; k < 8; k++)
                    if (k < wid) pos += __popc(sball[tx][k]);
                pos += __popc(sball[tx][wid] & lmask);
                g_tlist[((row * TX + tx) * SEGS + seg) * CAP + pos] = i;
            }
        }
        __syncthreads();
        if (tid < TX) {
            int s = 0;
            #pragma unroll
            for (int k = 0; k < 8; k++) s += __popc(sball[tid][k]);
            sbase[tid] += s;
        }
        __syncthreads();
    }
    if (tid < TX) g_tcnt[(row * TX + tid) * SEGS + seg] = sbase[tid];
}

// Render: grid (TX, TY, ZSPLIT); 2 px/thread; sync-free loop via uniform __ldg.
// Last-z block reduces ZSPLIT partials in fixed order (deterministic).
__global__ __launch_bounds__(256) void render_kernel(
    const float* __restrict__ scale_f,
    const float* __restrict__ shift_f,
    float* __restrict__ out) {
    __shared__ int sLast;

    const int tid = threadIdx.x;
    const int bx = blockIdx.x, row = blockIdx.y, z = blockIdx.z;
    const int px = bx * TSX + (tid & 15), py = row * TSY + (tid >> 4);
    const float fpx = (float)px, fpy = (float)py;
    const int tileIdx = row * TX + bx;

    float aR1 = 0.f, aG1 = 0.f, aB1 = 0.f;
    float aR2 = 0.f, aG2 = 0.f, aB2 = 0.f;

    const int seg0 = z * (SEGS / ZSPLIT);
    #pragma unroll
    for (int s = 0; s < SEGS / ZSPLIT; s++) {
        const int seg = seg0 + s;
        const int cnt = g_tcnt[tileIdx * SEGS + seg];
        const int* lst = g_tlist + (tileIdx * SEGS + seg) * CAP;
        #pragma unroll 4
        for (int j = 0; j < cnt; j++) {
            int g = __ldg(lst + j);
            float4 A = __ldg(&g_parA[g]);
            float4 B = __ldg(&g_parB[g]);
            float  C = __ldg(&g_parC[g]);
            float dy  = A.y - fpy;
            float dx1 = A.x - fpx;
            float dx2 = dx1 - 16.0f;
            float cdyy = (B.x * dy) * dy;   // hc*dy^2 (shared between pixels)
            float bdy  = A.w * dy;          // b*dy (shared)
            float k1 = B.y - fmaf(A.z * dx1, dx1, fmaf(bdy, dx1, cdyy));
            float k2 = B.y - fmaf(A.z * dx2, dx2, fmaf(bdy, dx2, cdyy));
            float al1, al2;
            asm("ex2.approx.f32 %0, %1;" : "=f"(al1) : "f"(k1));
            asm("ex2.approx.f32 %0, %1;" : "=f"(al2) : "f"(k2));
            float w1 = (al1 >= (1.0f / 255.0f)) ? fminf(al1, 0.999f) : 0.0f;
            float w2 = (al2 >= (1.0f / 255.0f)) ? fminf(al2, 0.999f) : 0.0f;
            aR1 = fmaf(w1, B.z, aR1);  aR2 = fmaf(w2, B.z, aR2);
            aG1 = fmaf(w1, B.w, aG1);  aG2 = fmaf(w2, B.w, aG2);
            aB1 = fmaf(w1, C,   aB1);  aB2 = fmaf(w2, C,   aB2);
        }
    }

    const int idx = py * W + px;   // second pixel at idx+16
    g_part[z][0 * (H * W) + idx] = aR1;  g_part[z][0 * (H * W) + idx + 16] = aR2;
    g_part[z][1 * (H * W) + idx] = aG1;  g_part[z][1 * (H * W) + idx + 16] = aG2;
    g_part[z][2 * (H * W) + idx] = aB1;  g_part[z][2 * (H * W) + idx + 16] = aB2;

    // Elect last z-block for this tile; reduce partials in fixed z order.
    __threadfence();
    __syncthreads();
    if (tid == 0) sLast = atomicAdd(&g_done[tileIdx], 1);
    __syncthreads();
    if (sLast != ZSPLIT - 1) return;

    __threadfence();
    float sc = scale_f[0], sh = shift_f[0];
    #pragma unroll
    for (int c = 0; c < 3; c++) {
        #pragma unroll
        for (int p = 0; p < 2; p++) {
            int o = c * (H * W) + idx + p * 16;
            float v = ((g_part[0][o] + g_part[1][o]) + (g_part[2][o] + g_part[3][o]));
            out[o] = fmaf(v, sc, sh);
        }
    }
}

extern "C" void kernel_launch(void* const* d_in, const int* in_sizes, int n_in,
                              void* d_out, int out_size) {
    const float* xyz     = (const float*)d_in[0];
    const float* chol    = (const float*)d_in[1];
    const float* colors  = (const float*)d_in[2];
    const float* opacity = (const float*)d_in[3];
    const float* scale_f = (const float*)d_in[4];
    const float* shift_f = (const float*)d_in[5];
    float* out = (float*)d_out;

    prep_kernel<<<(NG + 255) / 256, 256>>>(xyz, chol, colors, opacity);
    bin_kernel<<<dim3(SEGS, TY), 256>>>();
    render_kernel<<<dim3(TX, TY, ZSPLIT), 256>>>(scale_f, shift_f, out);
}

// round 15
// speedup vs baseline: 1.3781x; 1.3781x over previous
#include <cuda_runtime.h>
#include <cuda_bf16.h>

#define NG 10000
#define W 256
#define H 256
#define TSX 32
#define TSY 16
#define TX 8               // tiles per row (32 px wide)
#define TY 16              // tile rows (16 px tall)
#define NTILE (TX * TY)    // 128
#define SEGS 8
#define SEGN (NG / SEGS)   // 1250
#define CAP  SEGN
#define ZSPLIT 4           // 2 segments per z-block

// Static device scratch (no dynamic allocation anywhere)
static __device__ float4 g_parA[NG];                  // cx, cy, ha*log2e, b*log2e
static __device__ float4 g_parB[NG];                  // hc*log2e, log2(op), colR, colG
static __device__ float  g_parC[NG];                  // colB
static __device__ int    g_rng[NG];                   // tx0|tx1<<4|ty0<<8|ty1<<12
static __device__ int    g_tlist[NTILE * SEGS * CAP]; // gid lists (4 B/entry)
static __device__ int    g_tcnt[NTILE * SEGS];
static __device__ float  g_part[ZSPLIT][3 * H * W];
static __device__ int    g_done[NTILE];

__device__ __forceinline__ float fast_tanh(float x) {
    float e;
    asm("ex2.approx.f32 %0, %1;" : "=f"(e) : "f"(x * 2.885390081777927f)); // 2*log2e
    float r;
    asm("rcp.approx.f32 %0, %1;" : "=f"(r) : "f"(1.0f + e));
    return 1.0f - 2.0f * r;
}

// Prep: params + tile ranges; resets per-tile counters (runs first in-stream).
__global__ __launch_bounds__(256) void prep_kernel(
    const float* __restrict__ xyz,
    const float* __restrict__ chol,
    const float* __restrict__ colors,
    const float* __restrict__ opacity) {
    int i = blockIdx.x * 256 + threadIdx.x;
    if (i < NTILE) g_done[i] = 0;
    if (i >= NG) return;
    const float LOG2E = 1.4426950408889634f;
    float cx = 0.5f * W * (fast_tanh(xyz[2 * i]) + 1.0f);
    float cy = 0.5f * H * (fast_tanh(xyz[2 * i + 1]) + 1.0f);
    float L0 = chol[3 * i] + 0.5f;
    float L1 = chol[3 * i + 1];
    float L2 = chol[3 * i + 2] + 0.5f;
    float cxx = L0 * L0;
    float cxy = L0 * L1;
    float cyy = L1 * L1 + L2 * L2;
    float det = cxx * cyy - cxy * cxy;
    float inv = 1.0f / det;
    float op = opacity[i];
    float T = __logf(255.0f * op) + 0.05f;

    int tx0 = 15, tx1 = 0, ty0 = 15, ty1 = 0;  // empty sentinel
    if (det > 0.0f && op > 0.0f && T > 0.0f) {
        float rx = sqrtf(2.0f * T * cxx) + 1.0f;
        float ry = sqrtf(2.0f * T * cyy) + 1.0f;
        float xlo = cx - rx, xhi = cx + rx;
        float ylo = cy - ry, yhi = cy + ry;
        if (xhi >= 0.0f && xlo <= (float)(W - 1) &&
            yhi >= 0.0f && ylo <= (float)(H - 1)) {
            tx0 = max(0, (int)floorf(xlo * (1.0f / TSX)));
            tx1 = min(TX - 1, (int)floorf(xhi * (1.0f / TSX)));
            ty0 = max(0, (int)floorf(ylo * (1.0f / TSY)));
            ty1 = min(TY - 1, (int)floorf(yhi * (1.0f / TSY)));
        }
    }
    g_rng[i]  = tx0 | (tx1 << 4) | (ty0 << 8) | (ty1 << 12);
    g_parA[i] = make_float4(cx, cy, 0.5f * cyy * inv * LOG2E, -cxy * inv * LOG2E);
    g_parB[i] = make_float4(0.5f * cxx * inv * LOG2E, __log2f(op),
                            colors[3 * i], colors[3 * i + 1]);
    g_parC[i] = colors[3 * i + 2];
}

// Binning: grid (SEGS, TY). Deterministic gid-ordered scatter into 8 tile lists.
__global__ __launch_bounds__(256) void bin_kernel() {
    const int seg = blockIdx.x, row = blockIdx.y;
    const int tid = threadIdx.x, lane = tid & 31, wid = tid >> 5;
    __shared__ unsigned sball[TX][9];
    __shared__ int sbase[TX];
    const int segBase = seg * SEGN;
    const unsigned lmask = (1u << lane) - 1u;

    if (tid < TX) sbase[tid] = 0;
    __syncthreads();

    for (int it = 0; it < (SEGN + 255) / 256; it++) {
        int i = segBase + it * 256 + tid;
        int rng = (i < segBase + SEGN) ? g_rng[i] : 0x0F00;
        int ty0 = (rng >> 8) & 15, ty1 = (rng >> 12) & 15;
        int t0 = rng & 15, t1 = (rng >> 4) & 15;
        bool pass = (ty0 <= row) && (row <= ty1);
        #pragma unroll
        for (int tx = 0; tx < TX; tx++) {
            unsigned b = __ballot_sync(0xffffffffu, pass && (t0 <= tx) && (tx <= t1));
            if (lane == 0) sball[tx][wid] = b;
        }
        __syncthreads();
        if (pass) {
            for (int tx = t0; tx <= t1; tx++) {
                int pos = sbase[tx];
                #pragma unroll
                for (int k = 0; k < 8; k++)
                    if (k < wid) pos += __popc(sball[tx][k]);
                pos += __popc(sball[tx][wid] & lmask);
                g_tlist[((row * TX + tx) * SEGS + seg) * CAP + pos] = i;
            }
        }
        __syncthreads();
        if (tid < TX) {
            int s = 0;
            #pragma unroll
            for (int k = 0; k < 8; k++) s += __popc(sball[tid][k]);
            sbase[tid] += s;
        }
        __syncthreads();
    }
    if (tid < TX) g_tcnt[(row * TX + tid) * SEGS + seg] = sbase[tid];
}

// Render: grid (TX, TY, ZSPLIT); smem-staged chunks; 2 px/thread (px, px+16).
// Last-z block reduces ZSPLIT partials in fixed order (deterministic).
__global__ __launch_bounds__(256) void render_kernel(
    const float* __restrict__ scale_f,
    const float* __restrict__ shift_f,
    float* __restrict__ out) {
    __shared__ float4 sA[256];
    __shared__ float4 sB[256];
    __shared__ float  sC[256];
    __shared__ int sLast;

    const int tid = threadIdx.x;
    const int bx = blockIdx.x, row = blockIdx.y, z = blockIdx.z;
    const int px = bx * TSX + (tid & 15), py = row * TSY + (tid >> 4);
    const float fpx = (float)px, fpy = (float)py;
    const int tileIdx = row * TX + bx;

    float aR1 = 0.f, aG1 = 0.f, aB1 = 0.f;
    float aR2 = 0.f, aG2 = 0.f, aB2 = 0.f;

    const int seg0 = z * (SEGS / ZSPLIT);
    #pragma unroll
    for (int s = 0; s < SEGS / ZSPLIT; s++) {
        const int seg = seg0 + s;
        const int cnt = g_tcnt[tileIdx * SEGS + seg];
        const int* lst = g_tlist + (tileIdx * SEGS + seg) * CAP;
        for (int base = 0; base < cnt; base += 256) {
            int i = base + tid;
            if (i < cnt) {
                int g = lst[i];
                sA[tid] = g_parA[g];
                sB[tid] = g_parB[g];
                sC[tid] = g_parC[g];
            }
            __syncthreads();
            int m = min(256, cnt - base);
            #pragma unroll 2
            for (int j = 0; j < m; j++) {
                float4 A = sA[j];
                float4 B = sB[j];
                float dy  = A.y - fpy;
                float dx1 = A.x - fpx;
                float dx2 = dx1 - 16.0f;
                float cdyy = (B.x * dy) * dy;   // hc*dy^2 (shared between pixels)
                float bdy  = A.w * dy;          // b*dy (shared)
                float k1 = B.y - fmaf(A.z * dx1, dx1, fmaf(bdy, dx1, cdyy));
                float k2 = B.y - fmaf(A.z * dx2, dx2, fmaf(bdy, dx2, cdyy));
                float al1, al2;
                asm("ex2.approx.f32 %0, %1;" : "=f"(al1) : "f"(k1));
                asm("ex2.approx.f32 %0, %1;" : "=f"(al2) : "f"(k2));
                float w1 = (al1 >= (1.0f / 255.0f)) ? fminf(al1, 0.999f) : 0.0f;
                float w2 = (al2 >= (1.0f / 255.0f)) ? fminf(al2, 0.999f) : 0.0f;
                aR1 = fmaf(w1, B.z, aR1);  aR2 = fmaf(w2, B.z, aR2);
                aG1 = fmaf(w1, B.w, aG1);  aG2 = fmaf(w2, B.w, aG2);
                aB1 = fmaf(w1, sC[j], aB1); aB2 = fmaf(w2, sC[j], aB2);
            }
            __syncthreads();
        }
    }

    const int idx = py * W + px;   // second pixel at idx+16
    g_part[z][0 * (H * W) + idx] = aR1;  g_part[z][0 * (H * W) + idx + 16] = aR2;
    g_part[z][1 * (H * W) + idx] = aG1;  g_part[z][1 * (H * W) + idx + 16] = aG2;
    g_part[z][2 * (H * W) + idx] = aB1;  g_part[z][2 * (H * W) + idx + 16] = aB2;

    // Elect last z-block for this tile; reduce partials in fixed z order.
    __threadfence();
    __syncthreads();
    if (tid == 0) sLast = atomicAdd(&g_done[tileIdx], 1);
    __syncthreads();
    if (sLast != ZSPLIT - 1) return;

    __threadfence();
    float sc = scale_f[0], sh = shift_f[0];
    #pragma unroll
    for (int c = 0; c < 3; c++) {
        #pragma unroll
        for (int p = 0; p < 2; p++) {
            int o = c * (H * W) + idx + p * 16;
            float v = ((g_part[0][o] + g_part[1][o]) + (g_part[2][o] + g_part[3][o]));
            out[o] = fmaf(v, sc, sh);
        }
    }
}

extern "C" void kernel_launch(void* const* d_in, const int* in_sizes, int n_in,
                              void* d_out, int out_size) {
    const float* xyz     = (const float*)d_in[0];
    const float* chol    = (const float*)d_in[1];
    const float* colors  = (const float*)d_in[2];
    const float* opacity = (const float*)d_in[3];
    const float* scale_f = (const float*)d_in[4];
    const float* shift_f = (const float*)d_in[5];
    float* out = (float*)d_out;

    prep_kernel<<<(NG + 255) / 256, 256>>>(xyz, chol, colors, opacity);
    bin_kernel<<<dim3(SEGS, TY), 256>>>();
    render_kernel<<<dim3(TX, TY, ZSPLIT), 256>>>(scale_f, shift_f, out);
}

// round 16
// speedup vs baseline: 1.8498x; 1.3423x over previous
#include <cuda_runtime.h>
#include <cuda_bf16.h>

#define NG 10000
#define W 256
#define H 256
#define TS 16
#define TX 16
#define TY 16
#define NTILE (TX * TY)
#define SEGS 8
#define SEGN (NG / SEGS)   // 1250
#define CAP  SEGN
#define ZSPLIT 4

// Static device scratch (no dynamic allocation anywhere)
static __device__ float4 g_parA[NG];                  // cx, cy, ha*log2e, b*log2e
static __device__ float4 g_parB[NG];                  // hc*log2e, log2(op), colR, colG
static __device__ float  g_parC[NG];                  // colB
static __device__ int    g_rng[NG];                   // tx0|tx1<<4|ty0<<8|ty1<<12
static __device__ int    g_tlist[NTILE * SEGS * CAP]; // gid lists
static __device__ int    g_tcnt[NTILE * SEGS];
static __device__ float  g_part[ZSPLIT][3 * H * W];

__device__ __forceinline__ float fast_tanh(float x) {
    float e;
    asm("ex2.approx.f32 %0, %1;" : "=f"(e) : "f"(x * 2.885390081777927f)); // 2*log2e
    float r;
    asm("rcp.approx.f32 %0, %1;" : "=f"(r) : "f"(1.0f + e));
    return 1.0f - 2.0f * r;
}

// Prep: params + tile ranges (16x16 tiles).
__global__ __launch_bounds__(256) void prep_kernel(
    const float* __restrict__ xyz,
    const float* __restrict__ chol,
    const float* __restrict__ colors,
    const float* __restrict__ opacity) {
    int i = blockIdx.x * 256 + threadIdx.x;
    if (i >= NG) return;
    const float LOG2E = 1.4426950408889634f;
    float cx = 0.5f * W * (fast_tanh(xyz[2 * i]) + 1.0f);
    float cy = 0.5f * H * (fast_tanh(xyz[2 * i + 1]) + 1.0f);
    float L0 = chol[3 * i] + 0.5f;
    float L1 = chol[3 * i + 1];
    float L2 = chol[3 * i + 2] + 0.5f;
    float cxx = L0 * L0;
    float cxy = L0 * L1;
    float cyy = L1 * L1 + L2 * L2;
    float det = cxx * cyy - cxy * cxy;
    float inv = 1.0f / det;
    float op = opacity[i];
    float T = __logf(255.0f * op) + 0.05f;

    int tx0 = 15, tx1 = 0, ty0 = 15, ty1 = 0;  // empty sentinel
    if (det > 0.0f && op > 0.0f && T > 0.0f) {
        float rx = sqrtf(2.0f * T * cxx) + 1.0f;
        float ry = sqrtf(2.0f * T * cyy) + 1.0f;
        float xlo = cx - rx, xhi = cx + rx;
        float ylo = cy - ry, yhi = cy + ry;
        if (xhi >= 0.0f && xlo <= (float)(W - 1) &&
            yhi >= 0.0f && ylo <= (float)(H - 1)) {
            tx0 = max(0, (int)floorf(xlo * (1.0f / TS)));
            tx1 = min(TX - 1, (int)floorf(xhi * (1.0f / TS)));
            ty0 = max(0, (int)floorf(ylo * (1.0f / TS)));
            ty1 = min(TY - 1, (int)floorf(yhi * (1.0f / TS)));
        }
    }
    g_rng[i]  = tx0 | (tx1 << 4) | (ty0 << 8) | (ty1 << 12);
    g_parA[i] = make_float4(cx, cy, 0.5f * cyy * inv * LOG2E, -cxy * inv * LOG2E);
    g_parB[i] = make_float4(0.5f * cxx * inv * LOG2E, __log2f(op),
                            colors[3 * i], colors[3 * i + 1]);
    g_parC[i] = colors[3 * i + 2];
}

// Binning: grid (SEGS, TY). Deterministic gid-ordered scatter into 16 tile lists.
__global__ __launch_bounds__(256) void bin_kernel() {
    const int seg = blockIdx.x, row = blockIdx.y;
    const int tid = threadIdx.x, lane = tid & 31, wid = tid >> 5;
    __shared__ unsigned sball[TX][9];
    __shared__ int sbase[TX];
    const int segBase = seg * SEGN;
    const unsigned lmask = (1u << lane) - 1u;

    if (tid < TX) sbase[tid] = 0;
    __syncthreads();

    for (int it = 0; it < (SEGN + 255) / 256; it++) {
        int i = segBase + it * 256 + tid;
        int rng = (i < segBase + SEGN) ? g_rng[i] : 0x0F00;
        int ty0 = (rng >> 8) & 15, ty1 = (rng >> 12) & 15;
        int t0 = rng & 15, t1 = (rng >> 4) & 15;
        bool pass = (ty0 <= row) && (row <= ty1);
        #pragma unroll
        for (int tx = 0; tx < TX; tx++) {
            unsigned b = __ballot_sync(0xffffffffu, pass && (t0 <= tx) && (tx <= t1));
            if (lane == 0) sball[tx][wid] = b;
        }
        __syncthreads();
        if (pass) {
            for (int tx = t0; tx <= t1; tx++) {
                int pos = sbase[tx];
                #pragma unroll
                for (int k = 0; k < 8; k++)
                    if (k < wid) pos += __popc(sball[tx][k]);
                pos += __popc(sball[tx][wid] & lmask);
                g_tlist[((row * TX + tx) * SEGS + seg) * CAP + pos] = i;
            }
        }
        __syncthreads();
        if (tid < TX) {
            int s = 0;
            #pragma unroll
            for (int k = 0; k < 8; k++) s += __popc(sball[tid][k]);
            sbase[tid] += s;
        }
        __syncthreads();
    }
    if (tid < TX) g_tcnt[(row * TX + tid) * SEGS + seg] = sbase[tid];
}

// Render: grid (TX, TY, ZSPLIT); 128 threads/block; 2 px/thread (px, px+8)
// inside the SAME 16x16 tile. Smem-staged 128-entry chunks.
__global__ __launch_bounds__(128) void render_kernel() {
    __shared__ float4 sA[128];
    __shared__ float4 sB[128];
    __shared__ float  sC[128];

    const int tid = threadIdx.x;
    const int bx = blockIdx.x, row = blockIdx.y, z = blockIdx.z;
    const int lx = tid & 7, ly = tid >> 3;            // 8 x 16
    const int px = bx * TS + lx, py = row * TS + ly;  // pair: (px, px+8)
    const float fpx = (float)px, fpy = (float)py;
    const int tileIdx = row * TX + bx;

    float aR1 = 0.f, aG1 = 0.f, aB1 = 0.f;
    float aR2 = 0.f, aG2 = 0.f, aB2 = 0.f;

    const int seg0 = z * (SEGS / ZSPLIT);
    #pragma unroll
    for (int s = 0; s < SEGS / ZSPLIT; s++) {
        const int seg = seg0 + s;
        const int cnt = g_tcnt[tileIdx * SEGS + seg];
        const int* lst = g_tlist + (tileIdx * SEGS + seg) * CAP;
        for (int base = 0; base < cnt; base += 128) {
            int i = base + tid;
            if (i < cnt) {
                int g = lst[i];
                sA[tid] = g_parA[g];
                sB[tid] = g_parB[g];
                sC[tid] = g_parC[g];
            }
            __syncthreads();
            int m = min(128, cnt - base);
            #pragma unroll 2
            for (int j = 0; j < m; j++) {
                float4 A = sA[j];
                float4 B = sB[j];
                float dy  = A.y - fpy;
                float dx1 = A.x - fpx;
                float dx2 = dx1 - 8.0f;
                float cdyy = (B.x * dy) * dy;   // hc*dy^2 (shared)
                float bdy  = A.w * dy;          // b*dy (shared)
                float k1 = B.y - fmaf(A.z * dx1, dx1, fmaf(bdy, dx1, cdyy));
                float k2 = B.y - fmaf(A.z * dx2, dx2, fmaf(bdy, dx2, cdyy));
                float al1, al2;
                asm("ex2.approx.f32 %0, %1;" : "=f"(al1) : "f"(k1));
                asm("ex2.approx.f32 %0, %1;" : "=f"(al2) : "f"(k2));
                float w1 = (al1 >= (1.0f / 255.0f)) ? fminf(al1, 0.999f) : 0.0f;
                float w2 = (al2 >= (1.0f / 255.0f)) ? fminf(al2, 0.999f) : 0.0f;
                aR1 = fmaf(w1, B.z, aR1);  aR2 = fmaf(w2, B.z, aR2);
                aG1 = fmaf(w1, B.w, aG1);  aG2 = fmaf(w2, B.w, aG2);
                aB1 = fmaf(w1, sC[j], aB1); aB2 = fmaf(w2, sC[j], aB2);
            }
            __syncthreads();
        }
    }

    const int idx = py * W + px;   // second pixel at idx+8
    g_part[z][0 * (H * W) + idx] = aR1;  g_part[z][0 * (H * W) + idx + 8] = aR2;
    g_part[z][1 * (H * W) + idx] = aG1;  g_part[z][1 * (H * W) + idx + 8] = aG2;
    g_part[z][2 * (H * W) + idx] = aB1;  g_part[z][2 * (H * W) + idx + 8] = aB2;
}

// Deterministic fixed-order reduction of partials + scale/shift.
__global__ __launch_bounds__(256) void finish_kernel(
    const float* __restrict__ scale_f,
    const float* __restrict__ shift_f,
    float* __restrict__ out) {
    int t = blockIdx.x * blockDim.x + threadIdx.x;  // float4 index
    const int n4 = 3 * H * W / 4;
    if (t >= n4) return;
    float s = scale_f[0], sh = shift_f[0];
    const float4* p0 = (const float4*)g_part[0];
    const float4* p1 = (const float4*)g_part[1];
    const float4* p2 = (const float4*)g_part[2];
    const float4* p3 = (const float4*)g_part[3];
    float4 a = p0[t], b = p1[t], c = p2[t], d = p3[t];
    float4 r;
    r.x = fmaf(((a.x + b.x) + (c.x + d.x)), s, sh);
    r.y = fmaf(((a.y + b.y) + (c.y + d.y)), s, sh);
    r.z = fmaf(((a.z + b.z) + (c.z + d.z)), s, sh);
    r.w = fmaf(((a.w + b.w) + (c.w + d.w)), s, sh);
    ((float4*)out)[t] = r;
}

extern "C" void kernel_launch(void* const* d_in, const int* in_sizes, int n_in,
                              void* d_out, int out_size) {
    const float* xyz     = (const float*)d_in[0];
    const float* chol    = (const float*)d_in[1];
    const float* colors  = (const float*)d_in[2];
    const float* opacity = (const float*)d_in[3];
    const float* scale_f = (const float*)d_in[4];
    const float* shift_f = (const float*)d_in[5];
    float* out = (float*)d_out;

    prep_kernel<<<(NG + 255) / 256, 256>>>(xyz, chol, colors, opacity);
    bin_kernel<<<dim3(SEGS, TY), 256>>>();
    render_kernel<<<dim3(TX, TY, ZSPLIT), 128>>>();
    finish_kernel<<<(3 * H * W / 4 + 255) / 256, 256>>>(scale_f, shift_f, out);
}

// round 17
// speedup vs baseline: 1.8780x; 1.0152x over previous
#include <cuda_runtime.h>
#include <cuda_bf16.h>

#define NG 10000
#define W 256
#define H 256
#define TS 16
#define TX 16
#define TY 16
#define NTILE (TX * TY)
#define SEGS 8
#define SEGN (NG / SEGS)   // 1250
#define CAP  SEGN
#define ZSPLIT 8           // 1 segment per z-block

// Static device scratch (no dynamic allocation anywhere)
static __device__ float4 g_parA[NG];                  // cx, cy, ha*log2e, b*log2e
static __device__ float4 g_parB[NG];                  // hc*log2e, log2(op), colR, colG
static __device__ float  g_parC[NG];                  // colB
static __device__ int    g_rng[NG];                   // tx0|tx1<<4|ty0<<8|ty1<<12
static __device__ int    g_tlist[NTILE * SEGS * CAP]; // gid lists
static __device__ int    g_tcnt[NTILE * SEGS];
static __device__ float  g_part[ZSPLIT][3 * H * W];

__device__ __forceinline__ float fast_tanh(float x) {
    float e;
    asm("ex2.approx.f32 %0, %1;" : "=f"(e) : "f"(x * 2.885390081777927f)); // 2*log2e
    float r;
    asm("rcp.approx.f32 %0, %1;" : "=f"(r) : "f"(1.0f + e));
    return 1.0f - 2.0f * r;
}

// Prep: params + tile ranges (16x16 tiles). Tight bbox: +0.5 px safety only.
__global__ __launch_bounds__(256) void prep_kernel(
    const float* __restrict__ xyz,
    const float* __restrict__ chol,
    const float* __restrict__ colors,
    const float* __restrict__ opacity) {
    int i = blockIdx.x * 256 + threadIdx.x;
    if (i >= NG) return;
    const float LOG2E = 1.4426950408889634f;
    float cx = 0.5f * W * (fast_tanh(xyz[2 * i]) + 1.0f);
    float cy = 0.5f * H * (fast_tanh(xyz[2 * i + 1]) + 1.0f);
    float L0 = chol[3 * i] + 0.5f;
    float L1 = chol[3 * i + 1];
    float L2 = chol[3 * i + 2] + 0.5f;
    float cxx = L0 * L0;
    float cxy = L0 * L1;
    float cyy = L1 * L1 + L2 * L2;
    float det = cxx * cyy - cxy * cxy;
    float inv = 1.0f / det;
    float op = opacity[i];
    float T = __logf(255.0f * op) + 0.02f;   // threshold sigma (+small fp margin)

    int tx0 = 15, tx1 = 0, ty0 = 15, ty1 = 0;  // empty sentinel
    if (det > 0.0f && op > 0.0f && T > 0.0f) {
        float rx = sqrtf(2.0f * T * cxx) + 0.5f;
        float ry = sqrtf(2.0f * T * cyy) + 0.5f;
        float xlo = cx - rx, xhi = cx + rx;
        float ylo = cy - ry, yhi = cy + ry;
        if (xhi >= 0.0f && xlo <= (float)(W - 1) &&
            yhi >= 0.0f && ylo <= (float)(H - 1)) {
            tx0 = max(0, (int)floorf(xlo * (1.0f / TS)));
            tx1 = min(TX - 1, (int)floorf(xhi * (1.0f / TS)));
            ty0 = max(0, (int)floorf(ylo * (1.0f / TS)));
            ty1 = min(TY - 1, (int)floorf(yhi * (1.0f / TS)));
        }
    }
    g_rng[i]  = tx0 | (tx1 << 4) | (ty0 << 8) | (ty1 << 12);
    g_parA[i] = make_float4(cx, cy, 0.5f * cyy * inv * LOG2E, -cxy * inv * LOG2E);
    g_parB[i] = make_float4(0.5f * cxx * inv * LOG2E, __log2f(op),
                            colors[3 * i], colors[3 * i + 1]);
    g_parC[i] = colors[3 * i + 2];
}

// Binning: grid (SEGS, TY). Deterministic gid-ordered scatter into 16 tile lists.
__global__ __launch_bounds__(256) void bin_kernel() {
    const int seg = blockIdx.x, row = blockIdx.y;
    const int tid = threadIdx.x, lane = tid & 31, wid = tid >> 5;
    __shared__ unsigned sball[TX][9];
    __shared__ int sbase[TX];
    const int segBase = seg * SEGN;
    const unsigned lmask = (1u << lane) - 1u;

    if (tid < TX) sbase[tid] = 0;
    __syncthreads();

    for (int it = 0; it < (SEGN + 255) / 256; it++) {
        int i = segBase + it * 256 + tid;
        int rng = (i < segBase + SEGN) ? g_rng[i] : 0x0F00;
        int ty0 = (rng >> 8) & 15, ty1 = (rng >> 12) & 15;
        int t0 = rng & 15, t1 = (rng >> 4) & 15;
        bool pass = (ty0 <= row) && (row <= ty1);
        #pragma unroll
        for (int tx = 0; tx < TX; tx++) {
            unsigned b = __ballot_sync(0xffffffffu, pass && (t0 <= tx) && (tx <= t1));
            if (lane == 0) sball[tx][wid] = b;
        }
        __syncthreads();
        if (pass) {
            for (int tx = t0; tx <= t1; tx++) {
                int pos = sbase[tx];
                #pragma unroll
                for (int k = 0; k < 8; k++)
                    if (k < wid) pos += __popc(sball[tx][k]);
                pos += __popc(sball[tx][wid] & lmask);
                g_tlist[((row * TX + tx) * SEGS + seg) * CAP + pos] = i;
            }
        }
        __syncthreads();
        if (tid < TX) {
            int s = 0;
            #pragma unroll
            for (int k = 0; k < 8; k++) s += __popc(sball[tid][k]);
            sbase[tid] += s;
        }
        __syncthreads();
    }
    if (tid < TX) g_tcnt[(row * TX + tid) * SEGS + seg] = sbase[tid];
}

// Render: grid (TX, TY, ZSPLIT); 64 threads/block; 4 px/thread (px, +4, +8, +12)
// inside the same 16x16 tile. Smem-staged 64-entry chunks; 1 segment per z.
__global__ __launch_bounds__(64) void render_kernel() {
    __shared__ float4 sA[64];
    __shared__ float4 sB[64];
    __shared__ float  sC[64];

    const int tid = threadIdx.x;
    const int bx = blockIdx.x, row = blockIdx.y, seg = blockIdx.z;
    const int lx = tid & 3, ly = tid >> 2;            // 4 x 16
    const int px = bx * TS + lx, py = row * TS + ly;  // quad: px, +4, +8, +12
    const float fpx = (float)px, fpy = (float)py;
    const int tileIdx = row * TX + bx;

    float aR0 = 0.f, aG0 = 0.f, aB0 = 0.f;
    float aR1 = 0.f, aG1 = 0.f, aB1 = 0.f;
    float aR2 = 0.f, aG2 = 0.f, aB2 = 0.f;
    float aR3 = 0.f, aG3 = 0.f, aB3 = 0.f;

    const int cnt = g_tcnt[tileIdx * SEGS + seg];
    const int* lst = g_tlist + (tileIdx * SEGS + seg) * CAP;
    for (int base = 0; base < cnt; base += 64) {
        int i = base + tid;
        if (i < cnt) {
            int g = lst[i];
            sA[tid] = g_parA[g];
            sB[tid] = g_parB[g];
            sC[tid] = g_parC[g];
        }
        __syncthreads();
        int m = min(64, cnt - base);
        #pragma unroll 2
        for (int j = 0; j < m; j++) {
            float4 A = sA[j];
            float4 B = sB[j];
            float C  = sC[j];
            float dy   = A.y - fpy;
            float cdyy = (B.x * dy) * dy;   // hc*dy^2 (shared across 4 px)
            float bdy  = A.w * dy;          // b*dy (shared)
            float base2 = B.y - cdyy;       // log2(op) - hc*dy^2 (shared)
            float dx0 = A.x - fpx;
            float dx1 = dx0 - 4.0f;
            float dx2 = dx0 - 8.0f;
            float dx3 = dx0 - 12.0f;
            float k0 = base2 - fmaf(A.z * dx0, dx0, bdy * dx0);
            float k1 = base2 - fmaf(A.z * dx1, dx1, bdy * dx1);
            float k2 = base2 - fmaf(A.z * dx2, dx2, bdy * dx2);
            float k3 = base2 - fmaf(A.z * dx3, dx3, bdy * dx3);
            float e0, e1, e2, e3;
            asm("ex2.approx.f32 %0, %1;" : "=f"(e0) : "f"(k0));
            asm("ex2.approx.f32 %0, %1;" : "=f"(e1) : "f"(k1));
            asm("ex2.approx.f32 %0, %1;" : "=f"(e2) : "f"(k2));
            asm("ex2.approx.f32 %0, %1;" : "=f"(e3) : "f"(k3));
            float w0 = (e0 >= (1.0f / 255.0f)) ? fminf(e0, 0.999f) : 0.0f;
            float w1 = (e1 >= (1.0f / 255.0f)) ? fminf(e1, 0.999f) : 0.0f;
            float w2 = (e2 >= (1.0f / 255.0f)) ? fminf(e2, 0.999f) : 0.0f;
            float w3 = (e3 >= (1.0f / 255.0f)) ? fminf(e3, 0.999f) : 0.0f;
            aR0 = fmaf(w0, B.z, aR0);  aR1 = fmaf(w1, B.z, aR1);
            aR2 = fmaf(w2, B.z, aR2);  aR3 = fmaf(w3, B.z, aR3);
            aG0 = fmaf(w0, B.w, aG0);  aG1 = fmaf(w1, B.w, aG1);
            aG2 = fmaf(w2, B.w, aG2);  aG3 = fmaf(w3, B.w, aG3);
            aB0 = fmaf(w0, C, aB0);    aB1 = fmaf(w1, C, aB1);
            aB2 = fmaf(w2, C, aB2);    aB3 = fmaf(w3, C, aB3);
        }
        __syncthreads();
    }

    const int idx = py * W + px;   // quad at idx, +4, +8, +12
    float* p0 = g_part[seg] + 0 * (H * W) + idx;
    float* p1 = g_part[seg] + 1 * (H * W) + idx;
    float* p2 = g_part[seg] + 2 * (H * W) + idx;
    p0[0] = aR0; p0[4] = aR1; p0[8] = aR2; p0[12] = aR3;
    p1[0] = aG0; p1[4] = aG1; p1[8] = aG2; p1[12] = aG3;
    p2[0] = aB0; p2[4] = aB1; p2[8] = aB2; p2[12] = aB3;
}

// Deterministic fixed-order reduction of the 8 partials + scale/shift.
__global__ __launch_bounds__(256) void finish_kernel(
    const float* __restrict__ scale_f,
    const float* __restrict__ shift_f,
    float* __restrict__ out) {
    int t = blockIdx.x * blockDim.x + threadIdx.x;  // float4 index
    const int n4 = 3 * H * W / 4;
    if (t >= n4) return;
    float s = scale_f[0], sh = shift_f[0];
    float4 a0 = ((const float4*)g_part[0])[t];
    float4 a1 = ((const float4*)g_part[1])[t];
    float4 a2 = ((const float4*)g_part[2])[t];
    float4 a3 = ((const float4*)g_part[3])[t];
    float4 a4 = ((const float4*)g_part[4])[t];
    float4 a5 = ((const float4*)g_part[5])[t];
    float4 a6 = ((const float4*)g_part[6])[t];
    float4 a7 = ((const float4*)g_part[7])[t];
    float4 r;
    r.x = fmaf(((a0.x + a1.x) + (a2.x + a3.x)) + ((a4.x + a5.x) + (a6.x + a7.x)), s, sh);
    r.y = fmaf(((a0.y + a1.y) + (a2.y + a3.y)) + ((a4.y + a5.y) + (a6.y + a7.y)), s, sh);
    r.z = fmaf(((a0.z + a1.z) + (a2.z + a3.z)) + ((a4.z + a5.z) + (a6.z + a7.z)), s, sh);
    r.w = fmaf(((a0.w + a1.w) + (a2.w + a3.w)) + ((a4.w + a5.w) + (a6.w + a7.w)), s, sh);
    ((float4*)out)[t] = r;
}

extern "C" void kernel_launch(void* const* d_in, const int* in_sizes, int n_in,
                              void* d_out, int out_size) {
    const float* xyz     = (const float*)d_in[0];
    const float* chol    = (const float*)d_in[1];
    const float* colors  = (const float*)d_in[2];
    const float* opacity = (const float*)d_in[3];
    const float* scale_f = (const float*)d_in[4];
    const float* shift_f = (const float*)d_in[5];
    float* out = (float*)d_out;

    prep_kernel<<<(NG + 255) / 256, 256>>>(xyz, chol, colors, opacity);
    bin_kernel<<<dim3(SEGS, TY), 256>>>();
    render_kernel<<<dim3(TX, TY, ZSPLIT), 64>>>();
    finish_kernel<<<(3 * H * W / 4 + 255) / 256, 256>>>(scale_f, shift_f, out);
}